// round 16
// baseline (speedup 1.0000x reference)
#include <cuda_runtime.h>
#include <math.h>

// Problem constants
#define LQ 128     // sequence length
#define TT 127     // T = L-1 output rows
#define EE 256     // embedding dim
#define HH 512     // hidden
#define G4 2048    // 4*H gates
#define VV 32000   // vocab
#define KH2 1024   // 2*H

#define NB 128     // persistent scan blocks (one per SM, all co-resident)
#define NT 256     // threads per scan block
#define TP 192     // padded t-columns in k-major global h (covers tile overrun)

// ---------------- device scratch (no allocs allowed) ----------------
__device__ float g_gxf[LQ][G4];        // emb @ W_ih_f^T + b_f
__device__ float g_gxb[LQ][G4];        // emb @ W_ih_b^T + b_b
__device__ float g_hf_all[TT][HH];     // forward hidden states
__device__ float g_hb_final[TT][HH];   // final backward hidden per row t
__device__ float g_hbT[2][HH][TP];     // double-buffered backward h, K-MAJOR
__device__ float g_hfwd[2][HH];        // double-buffered forward h
__device__ unsigned g_cnt;             // grid barrier arrive counter
__device__ unsigned g_gen;             // grid barrier generation

__device__ __forceinline__ float sigmoidf_(float x) {
    return 1.f / (1.f + expf(-x));
}

__device__ __forceinline__ unsigned long long fma2_(unsigned long long a,
                                                    unsigned long long b,
                                                    unsigned long long c) {
    unsigned long long d;
    asm("fma.rn.f32x2 %0, %1, %2, %3;" : "=l"(d) : "l"(a), "l"(b), "l"(c));
    return d;
}

__device__ __forceinline__ float lo_(unsigned long long p) {
    return __uint_as_float((unsigned)(p & 0xffffffffull));
}
__device__ __forceinline__ float hi_(unsigned long long p) {
    return __uint_as_float((unsigned)(p >> 32));
}
__device__ __forceinline__ unsigned long long dup_(float x) {
    unsigned long long d;
    asm("mov.b64 %0, {%1, %1};" : "=l"(d) : "r"(__float_as_uint(x)));
    return d;
}

__device__ __forceinline__ void cp_async16_(void* smem, const void* gmem) {
    unsigned saddr = (unsigned)__cvta_generic_to_shared(smem);
    asm volatile("cp.async.cg.shared.global [%0], [%1], 16;\n"
                 :: "r"(saddr), "l"(gmem) : "memory");
}
#define CP_COMMIT() asm volatile("cp.async.commit_group;\n" ::: "memory")
#define CP_WAIT0()  asm volatile("cp.async.wait_group 0;\n" ::: "memory")

// ---------------- init: zero state + barrier vars ----------------
__global__ void init_kernel() {
    int idx = blockIdx.x * blockDim.x + threadIdx.x;
    int stride = gridDim.x * blockDim.x;
    float* h0 = &g_hbT[0][0][0];
    for (int i = idx; i < HH * TP; i += stride) h0[i] = 0.f;
    if (idx < HH) g_hfwd[0][idx] = 0.f;
    if (idx == 0) { g_cnt = 0u; g_gen = 0u; }
}

// ---------------- gather + input GEMM (both directions) ----------------
__global__ void input_gemm_kernel(const int* __restrict__ x,
                                  const float* __restrict__ emb,
                                  const float* __restrict__ Wf,
                                  const float* __restrict__ bif,
                                  const float* __restrict__ bhf,
                                  const float* __restrict__ Wb,
                                  const float* __restrict__ bib,
                                  const float* __restrict__ bhb) {
    __shared__ float sW[16][EE];
    bool isB = (blockIdx.x >= 128);
    int j0 = (isB ? (blockIdx.x - 128) : blockIdx.x) * 16;
    const float* W  = isB ? Wb  : Wf;
    const float* bi = isB ? bib : bif;
    const float* bh = isB ? bhb : bhf;
    int tid = threadIdx.x;  // 128 threads

    for (int u = tid; u < 16 * EE; u += 128)
        sW[u >> 8][u & 255] = W[(j0 + (u >> 8)) * EE + (u & 255)];
    __syncthreads();

    int t = tid;
    int tok = x[t];
    const float* er = emb + (long)tok * EE;
    float acc[16];
#pragma unroll
    for (int r = 0; r < 16; r++) acc[r] = 0.f;

    for (int e = 0; e < EE; e += 4) {
        float4 e4 = *(const float4*)(er + e);
#pragma unroll
        for (int r = 0; r < 16; r++) {
            float4 w4 = *(const float4*)&sW[r][e];
            acc[r] += e4.x * w4.x + e4.y * w4.y + e4.z * w4.z + e4.w * w4.w;
        }
    }
    float* gx = isB ? &g_gxb[t][0] : &g_gxf[t][0];
#pragma unroll
    for (int r = 0; r < 16; r++) {
        int j = j0 + r;
        gx[j] = acc[r] + bi[j] + bh[j];
    }
}

// ---------------- persistent LSTM scan kernel ----------------
// 128 blocks, each owns 4 hidden dims (16 gate rows per direction).
// W_b and the staged h tile are K-MAJOR in smem: one LDS.128 yields 4 rows
// (one gate's 4 q-dims) or 4 t's at the same k -> rank-1 outer products.
// Warp = (k-quarter kq, row-half rh); lane = (rq: gate within half, tq: t-quad).
// Lane tile 4q x 4t, fma.rn.f32x2 packed over q-pairs; k-split partials
// combined through smem (no shfl).
extern __shared__ float dyn_smem[];

__global__ void __launch_bounds__(NT, 1)
scan_kernel(const float* __restrict__ Whf, const float* __restrict__ Whb) {
    float* sWbT = dyn_smem;              // [512][16] k-major W_b   32 KB
    float* sWf  = sWbT + 512 * 16;       // [16][512] row-major W_f 32 KB
    float* shT  = sWf + 16 * HH;         // [512][64] k-major h    128 KB
    __shared__ float sgp[4][4][64][4];   // partials [kq][gate][tcol][q] 16 KB
    __shared__ float scb[TT][4];         // backward c, block's 4 dims
    __shared__ float shf[HH];            // forward h
    __shared__ float sgf[16];            // forward gate staging
    __shared__ float scf[4];             // forward c

    int tid = threadIdx.x;
    int k0 = blockIdx.x * 4;

    // stage W once: sWbT[k][r] = Whb[(gate*HH + k0 + q)*HH + k], r = gate*4+q
    for (int u = tid; u < 16 * 512; u += NT) {
        int k = u >> 4, r = u & 15;
        int j = (r >> 2) * HH + k0 + (r & 3);
        sWbT[k * 16 + r] = Whb[(long)j * HH + k];
    }
    for (int u = tid; u < 16 * HH; u += NT) {
        int r = u >> 9, k = u & (HH - 1);
        int j = (r >> 2) * HH + k0 + (r & 3);
        sWf[r * HH + k] = Whf[(long)j * HH + k];
    }
    for (int u = tid; u < TT; u += NT) {
        scb[u][0] = 0.f; scb[u][1] = 0.f; scb[u][2] = 0.f; scb[u][3] = 0.f;
    }
    if (tid < 4) scf[tid] = 0.f;
    __syncthreads();

    int lane = tid & 31;
    int warp = tid >> 5;     // 8 warps
    int kq   = warp >> 1;    // k-quarter (128 k each)
    int rh   = warp & 1;     // row half: gates 0-1 / 2-3
    int rq   = lane & 1;     // gate within half
    int tq   = lane >> 1;    // 0..15 -> t cols 4*tq .. 4*tq+3
    int gate = rh * 2 + rq;  // 0..3

    for (int s = 0; s < TT; s++) {
        int p = s & 1, p2 = p ^ 1;
        int tb0 = s & ~3;

        // ---- issue async stage of first tile (overlaps forward chain) ----
        for (int u = tid; u < 512 * 16; u += NT) {
            int k = u >> 4, seg = u & 15;
            cp_async16_(shT + k * 64 + seg * 4, &g_hbT[p][k][tb0 + seg * 4]);
        }
        CP_COMMIT();

        // ======== forward chain (16 rows) ========
        for (int u = tid; u < HH; u += NT) shf[u] = g_hfwd[p][u];
        __syncthreads();
        {
            int r0 = 2 * warp;   // warp handles rows r0, r0+1
            float a0 = 0.f, a1 = 0.f;
            const float* w0 = sWf + r0 * HH;
            const float* w1 = w0 + HH;
#pragma unroll
            for (int m = 0; m < 16; m++) {
                float h = shf[lane + 32 * m];
                a0 += w0[lane + 32 * m] * h;
                a1 += w1[lane + 32 * m] * h;
            }
#pragma unroll
            for (int off = 16; off >= 1; off >>= 1) {
                a0 += __shfl_xor_sync(0xffffffffu, a0, off);
                a1 += __shfl_xor_sync(0xffffffffu, a1, off);
            }
            if (lane == 0) { sgf[r0] = a0; sgf[r0 + 1] = a1; }
        }
        __syncthreads();
        if (tid < 4) {
            int q = tid, jb = k0 + q;
            float gi = sgf[0 * 4 + q] + g_gxf[s][jb];
            float gf = sgf[1 * 4 + q] + g_gxf[s][HH + jb];
            float gg = sgf[2 * 4 + q] + g_gxf[s][2 * HH + jb];
            float go = sgf[3 * 4 + q] + g_gxf[s][3 * HH + jb];
            float c  = scf[q];
            float cn = sigmoidf_(gf) * c + sigmoidf_(gi) * tanhf(gg);
            float hn = sigmoidf_(go) * tanhf(cn);
            scf[q] = cn;
            g_hfwd[p2][jb]  = hn;
            g_hf_all[s][jb] = hn;
        }

        // ---- wait for first tile stage ----
        CP_WAIT0();
        __syncthreads();

        // ======== backward prefix LSTMs ========
        for (int tb = tb0; tb < TT; tb += 64) {
            // rank-1 micro-tile: gate's 4 q x 4 t over this warp's k-quarter
            unsigned long long a00 = 0, a01 = 0, a02 = 0, a03 = 0;
            unsigned long long a10 = 0, a11 = 0, a12 = 0, a13 = 0;
            const float* wp = sWbT + (kq * 128) * 16 + (rh * 8 + rq * 4);
            const float* hp = shT + (kq * 128) * 64 + 4 * tq;
#pragma unroll 4
            for (int k = 0; k < 128; k++) {
                float4 w4 = *(const float4*)wp;  wp += 16;
                float4 h4 = *(const float4*)hp;  hp += 64;
                unsigned long long w01 = *(const unsigned long long*)&w4.x;
                unsigned long long w23 = *(const unsigned long long*)&w4.z;
                unsigned long long h0 = dup_(h4.x), h1 = dup_(h4.y);
                unsigned long long h2 = dup_(h4.z), h3 = dup_(h4.w);
                a00 = fma2_(w01, h0, a00);  a10 = fma2_(w23, h0, a10);
                a01 = fma2_(w01, h1, a01);  a11 = fma2_(w23, h1, a11);
                a02 = fma2_(w01, h2, a02);  a12 = fma2_(w23, h2, a12);
                a03 = fma2_(w01, h3, a03);  a13 = fma2_(w23, h3, a13);
            }
            // write k-quarter partials (q0..q3 of this gate, 4 t's)
            {
                float4* dst = (float4*)&sgp[kq][gate][4 * tq][0];
                dst[0] = make_float4(lo_(a00), hi_(a00), lo_(a10), hi_(a10));
                dst[1] = make_float4(lo_(a01), hi_(a01), lo_(a11), hi_(a11));
                dst[2] = make_float4(lo_(a02), hi_(a02), lo_(a12), hi_(a12));
                dst[3] = make_float4(lo_(a03), hi_(a03), lo_(a13), hi_(a13));
            }
            __syncthreads();   // sgp ready; shT reads done

            // issue next tile's stage (overlaps pointwise update)
            int tn = tb + 64;
            if (tn < TT) {
                for (int u = tid; u < 512 * 16; u += NT) {
                    int k = u >> 4, seg = u & 15;
                    cp_async16_(shT + k * 64 + seg * 4,
                                &g_hbT[p][k][tn + seg * 4]);
                }
                CP_COMMIT();
            }

            // pointwise LSTM update over valid t range
            int v0 = (tb > s) ? tb : s;
            int vend = (tb + 64 < TT) ? tb + 64 : TT;
            int cnt = vend - v0;
            if (tid < 4 * cnt) {
                int tt = tid >> 2, q = tid & 3;
                int t = v0 + tt;
                int tc = t - tb;
                int u = t - s;
                int jb = k0 + q;
                float gi = sgp[0][0][tc][q] + sgp[1][0][tc][q]
                         + sgp[2][0][tc][q] + sgp[3][0][tc][q] + g_gxb[u][jb];
                float gf = sgp[0][1][tc][q] + sgp[1][1][tc][q]
                         + sgp[2][1][tc][q] + sgp[3][1][tc][q] + g_gxb[u][HH + jb];
                float gg = sgp[0][2][tc][q] + sgp[1][2][tc][q]
                         + sgp[2][2][tc][q] + sgp[3][2][tc][q] + g_gxb[u][2 * HH + jb];
                float go = sgp[0][3][tc][q] + sgp[1][3][tc][q]
                         + sgp[2][3][tc][q] + sgp[3][3][tc][q] + g_gxb[u][3 * HH + jb];
                float c  = scb[t][q];
                float cn = sigmoidf_(gf) * c + sigmoidf_(gi) * tanhf(gg);
                float hn = sigmoidf_(go) * tanhf(cn);
                scb[t][q] = cn;
                g_hbT[p2][jb][t] = hn;
                if (t == s) g_hb_final[t][jb] = hn;
            }
            if (tn < TT) CP_WAIT0();
            __syncthreads();
        }

        // ======== grid barrier (acq_rel arrive, release/acquire hand-off) ====
        if (tid == 0) {
            unsigned a;
            asm volatile("fence.acq_rel.gpu;" ::: "memory");
            asm volatile("atom.acq_rel.gpu.add.u32 %0, [%1], %2;"
                         : "=r"(a) : "l"(&g_cnt), "r"(1u) : "memory");
            if (a == NB - 1) {
                asm volatile("st.relaxed.gpu.u32 [%0], %1;"
                             :: "l"(&g_cnt), "r"(0u) : "memory");
                asm volatile("st.release.gpu.u32 [%0], %1;"
                             :: "l"(&g_gen), "r"((unsigned)(s + 1)) : "memory");
            } else {
                unsigned g;
                do {
                    asm volatile("ld.acquire.gpu.u32 %0, [%1];"
                                 : "=r"(g) : "l"(&g_gen) : "memory");
                } while (g < (unsigned)(s + 1));
            }
        }
        __syncthreads();
    }
}

// ---------------- final FC: logits = [hf|hb] @ fc_w^T + fc_b ----------------
// Tile 64 t x 128 v, 256 threads, micro 8t x 4v (v strided by 32),
// f32x2 packed over k-pairs. Rows stride 18 -> 2-phase-floor LDS.64.
#define FCT 64
#define FCV 128
#define FCK 16
#define FCP 18
__device__ __forceinline__ float unpack_sum_(unsigned long long p) {
    return lo_(p) + hi_(p);
}
__global__ void __launch_bounds__(256, 2)
fc_kernel(const float* __restrict__ fcw,
          const float* __restrict__ fcb,
          float* __restrict__ out) {
    __shared__ float As[FCT][FCP];
    __shared__ float Bs[FCV][FCP];
    int tid = threadIdx.x;  // 256
    int tg  = tid >> 5;     // 0..7 -> t rows tg*8..+8
    int vg  = tid & 31;     // v lanes, strided by 32
    int tbase = blockIdx.y * FCT;
    int vbase = blockIdx.x * FCV;

    unsigned long long acc2[8][4];
#pragma unroll
    for (int j = 0; j < 8; j++)
#pragma unroll
        for (int c = 0; c < 4; c++) acc2[j][c] = 0ull;

    for (int kc = 0; kc < KH2; kc += FCK) {
        // stage A: 64 x 16 (one float4 per thread)
        {
            int tt = tid >> 2, kq2 = tid & 3;
            int t = tbase + tt;
            int k = kc + 4 * kq2;
            float4 a = make_float4(0.f, 0.f, 0.f, 0.f);
            if (t < TT)
                a = (k < HH) ? *(const float4*)&g_hf_all[t][k]
                             : *(const float4*)&g_hb_final[t][k - HH];
            *(float2*)&As[tt][4 * kq2]     = make_float2(a.x, a.y);
            *(float2*)&As[tt][4 * kq2 + 2] = make_float2(a.z, a.w);
        }
        // stage B: 128 x 16 (two float4 per thread)
        for (int u = tid; u < 512; u += 256) {
            int vv = u >> 2, kq2 = u & 3;
            float4 b = *(const float4*)&fcw[(long)(vbase + vv) * KH2 + kc + 4 * kq2];
            *(float2*)&Bs[vv][4 * kq2]     = make_float2(b.x, b.y);
            *(float2*)&Bs[vv][4 * kq2 + 2] = make_float2(b.z, b.w);
        }
        __syncthreads();

#pragma unroll
        for (int k2 = 0; k2 < FCK / 2; k2++) {
            unsigned long long a2[8], b2[4];
#pragma unroll
            for (int j = 0; j < 8; j++)
                a2[j] = *(const unsigned long long*)&As[tg * 8 + j][2 * k2];
#pragma unroll
            for (int c = 0; c < 4; c++)
                b2[c] = *(const unsigned long long*)&Bs[vg + 32 * c][2 * k2];
#pragma unroll
            for (int j = 0; j < 8; j++)
#pragma unroll
                for (int c = 0; c < 4; c++)
                    acc2[j][c] = fma2_(a2[j], b2[c], acc2[j][c]);
        }
        __syncthreads();
    }

#pragma unroll
    for (int j = 0; j < 8; j++) {
        int t = tbase + tg * 8 + j;
        if (t >= TT) continue;
#pragma unroll
        for (int c = 0; c < 4; c++) {
            int v = vbase + vg + 32 * c;
            out[(long)t * VV + v] = unpack_sum_(acc2[j][c]) + fcb[v];
        }
    }
}

// ---------------- launch ----------------
extern "C" void kernel_launch(void* const* d_in, const int* in_sizes, int n_in,
                              void* d_out, int out_size) {
    const int*   x      = (const int*)d_in[0];
    const float* emb    = (const float*)d_in[1];
    const float* W_ih_f = (const float*)d_in[2];
    const float* W_hh_f = (const float*)d_in[3];
    const float* b_ih_f = (const float*)d_in[4];
    const float* b_hh_f = (const float*)d_in[5];
    const float* W_ih_b = (const float*)d_in[6];
    const float* W_hh_b = (const float*)d_in[7];
    const float* b_ih_b = (const float*)d_in[8];
    const float* b_hh_b = (const float*)d_in[9];
    const float* fc_w   = (const float*)d_in[10];
    const float* fc_b   = (const float*)d_in[11];
    float* out = (float*)d_out;

    const int dynBytes = (512 * 16 + 16 * HH + 512 * 64) * (int)sizeof(float);
    cudaFuncSetAttribute(scan_kernel,
                         cudaFuncAttributeMaxDynamicSharedMemorySize, dynBytes);

    init_kernel<<<128, 256>>>();
    input_gemm_kernel<<<256, 128>>>(x, emb, W_ih_f, b_ih_f, b_hh_f,
                                    W_ih_b, b_ih_b, b_hh_b);
    scan_kernel<<<NB, NT, dynBytes>>>(W_hh_f, W_hh_b);
    fc_kernel<<<dim3(VV / FCV, (TT + FCT - 1) / FCT), 256>>>(fc_w, fc_b, out);
}